// round 3
// baseline (speedup 1.0000x reference)
#include <cuda_runtime.h>
#include <math.h>

#define N_NODES 100000
#define N_EDGES 3200000
#define FULL 0xffffffffu

// ---------------- static scratch (no allocation allowed) ----------------
__device__ float g_feat[N_NODES * 128];   // per-layer transformed features
__device__ float g_h[N_NODES * 128];      // layer-1 output
__device__ float g_el[N_NODES * 4];
__device__ float g_er[N_NODES * 4];
__device__ int   g_deg[N_NODES];
__device__ int   g_off[N_NODES + 1];
__device__ int   g_cur[N_NODES];
__device__ int   g_perm[N_EDGES];

// ---------------- CSR build ----------------
__global__ void zero_deg_kernel(int n) {
    int i = blockIdx.x * blockDim.x + threadIdx.x;
    if (i < n) g_deg[i] = 0;
}

__global__ void hist_kernel(const int* __restrict__ dst, int e) {
    int i = blockIdx.x * blockDim.x + threadIdx.x;
    if (i < e) atomicAdd(&g_deg[dst[i]], 1);
}

__global__ void scan_kernel(int n) {
    __shared__ int part[1024];
    int tid = threadIdx.x;
    int chunk = (n + 1023) / 1024;
    int b = tid * chunk;
    int e = min(b + chunk, n);
    int s = 0;
    for (int i = b; i < e; i++) s += g_deg[i];
    part[tid] = s;
    __syncthreads();
    for (int off = 1; off < 1024; off <<= 1) {
        int v = (tid >= off) ? part[tid - off] : 0;
        __syncthreads();
        part[tid] += v;
        __syncthreads();
    }
    int run = tid ? part[tid - 1] : 0;
    for (int i = b; i < e; i++) {
        g_off[i] = run;
        g_cur[i] = run;
        run += g_deg[i];
    }
    if (tid == 0) g_off[n] = part[1023];
}

__global__ void scatter_kernel(const int* __restrict__ dst, int e) {
    int i = blockIdx.x * blockDim.x + threadIdx.x;
    if (i < e) {
        int p = atomicAdd(&g_cur[dst[i]], 1);
        g_perm[p] = i;
    }
}

// ---------------- GEMM + fused el/er ----------------
// Block = 256 threads = 8 warps; each warp computes 4 rows x 128 cols.
// Lane cg owns cols [cg*4, cg*4+3] (within head cg>>3). W rows are L1-resident.
__global__ __launch_bounds__(256) void gemm_attn_kernel(
    const float* __restrict__ h, const float* __restrict__ W,
    const float* __restrict__ al, const float* __restrict__ ar,
    float* __restrict__ feat, float* __restrict__ el, float* __restrict__ er,
    int n)
{
    int warp = threadIdx.x >> 5;
    int cg   = threadIdx.x & 31;
    int row0 = (blockIdx.x * 8 + warp) * 4;
    if (row0 >= n) return;

    const float4* W4 = (const float4*)W;
    float acc[4][4];
    #pragma unroll
    for (int r = 0; r < 4; r++) { acc[r][0] = acc[r][1] = acc[r][2] = acc[r][3] = 0.f; }

    for (int k = 0; k < 128; k += 4) {
        float hb[4][4];
        #pragma unroll
        for (int r = 0; r < 4; r++) {
            float4 t = *(const float4*)(h + (size_t)(row0 + r) * 128 + k);
            hb[r][0] = t.x; hb[r][1] = t.y; hb[r][2] = t.z; hb[r][3] = t.w;
        }
        #pragma unroll
        for (int kk = 0; kk < 4; kk++) {
            float4 w = __ldg(&W4[(k + kk) * 32 + cg]);
            #pragma unroll
            for (int r = 0; r < 4; r++) {
                acc[r][0] = fmaf(hb[r][kk], w.x, acc[r][0]);
                acc[r][1] = fmaf(hb[r][kk], w.y, acc[r][1]);
                acc[r][2] = fmaf(hb[r][kk], w.z, acc[r][2]);
                acc[r][3] = fmaf(hb[r][kk], w.w, acc[r][3]);
            }
        }
    }

    float4 al4 = __ldg(&((const float4*)al)[cg]);
    float4 ar4 = __ldg(&((const float4*)ar)[cg]);

    #pragma unroll
    for (int r = 0; r < 4; r++) {
        float pl = acc[r][0] * al4.x + acc[r][1] * al4.y + acc[r][2] * al4.z + acc[r][3] * al4.w;
        float pr = acc[r][0] * ar4.x + acc[r][1] * ar4.y + acc[r][2] * ar4.z + acc[r][3] * ar4.w;
        #pragma unroll
        for (int off = 4; off; off >>= 1) {
            pl += __shfl_down_sync(FULL, pl, off);
            pr += __shfl_down_sync(FULL, pr, off);
        }
        if ((cg & 7) == 0) {
            int hl = cg >> 3;
            el[(size_t)(row0 + r) * 4 + hl] = pl;
            er[(size_t)(row0 + r) * 4 + hl] = pr;
        }
        float4 o;
        o.x = acc[r][0]; o.y = acc[r][1]; o.z = acc[r][2]; o.w = acc[r][3];
        ((float4*)feat)[(size_t)(row0 + r) * 32 + cg] = o;
    }
}

// ---------------- per-node softmax + aggregation ----------------
// One warp per destination node. Pass 1: lane-parallel online softmax per head,
// warp-merged. Pass 2: all 32 lanes cooperatively gather feat[src] (512B/edge)
// and FMA into register accumulators. No atomics.
__device__ __forceinline__ void merge_ms(float& m, float& s, int off) {
    float om = __shfl_down_sync(FULL, m, off);
    float os = __shfl_down_sync(FULL, s, off);
    float nm = fmaxf(m, om);
    // fmaxf(NaN, -88) == -88 handles the (-inf - -inf) case safely
    s = s * __expf(fmaxf(m - nm, -88.f)) + os * __expf(fmaxf(om - nm, -88.f));
    m = nm;
}

__global__ __launch_bounds__(256) void aggregate_kernel(
    const float* __restrict__ feat, const float* __restrict__ el,
    const float* __restrict__ er, const int* __restrict__ srcIdx,
    const float* __restrict__ ew, const float* __restrict__ bias,
    float* __restrict__ out, int n)
{
    int warp = threadIdx.x >> 5;
    int lane = threadIdx.x & 31;
    int node = blockIdx.x * 8 + warp;
    if (node >= n) return;

    int beg = g_off[node];
    int end = g_off[node + 1];

    float4 erv = *(const float4*)(er + (size_t)node * 4);

    // pass 1: online softmax stats per head (lane-strided over edges)
    float m0 = -INFINITY, m1 = -INFINITY, m2 = -INFINITY, m3 = -INFINITY;
    float s0 = 0.f, s1 = 0.f, s2 = 0.f, s3 = 0.f;
    for (int j = beg + lane; j < end; j += 32) {
        int e = g_perm[j];
        int s = srcIdx[e];
        float4 elv = *(const float4*)(el + (size_t)s * 4);
        float v;
        v = elv.x + erv.x; v = v > 0.f ? v : 0.2f * v;
        if (v <= m0) s0 += __expf(v - m0); else { s0 = s0 * __expf(m0 - v) + 1.f; m0 = v; }
        v = elv.y + erv.y; v = v > 0.f ? v : 0.2f * v;
        if (v <= m1) s1 += __expf(v - m1); else { s1 = s1 * __expf(m1 - v) + 1.f; m1 = v; }
        v = elv.z + erv.z; v = v > 0.f ? v : 0.2f * v;
        if (v <= m2) s2 += __expf(v - m2); else { s2 = s2 * __expf(m2 - v) + 1.f; m2 = v; }
        v = elv.w + erv.w; v = v > 0.f ? v : 0.2f * v;
        if (v <= m3) s3 += __expf(v - m3); else { s3 = s3 * __expf(m3 - v) + 1.f; m3 = v; }
    }
    #pragma unroll
    for (int off = 16; off; off >>= 1) {
        merge_ms(m0, s0, off);
        merge_ms(m1, s1, off);
        merge_ms(m2, s2, off);
        merge_ms(m3, s3, off);
    }
    m0 = __shfl_sync(FULL, m0, 0); s0 = __shfl_sync(FULL, s0, 0);
    m1 = __shfl_sync(FULL, m1, 0); s1 = __shfl_sync(FULL, s1, 0);
    m2 = __shfl_sync(FULL, m2, 0); s2 = __shfl_sync(FULL, s2, 0);
    m3 = __shfl_sync(FULL, m3, 0); s3 = __shfl_sync(FULL, s3, 0);

    float inv0 = 1.f / fmaxf(s0, 1e-20f);
    float inv1 = 1.f / fmaxf(s1, 1e-20f);
    float inv2 = 1.f / fmaxf(s2, 1e-20f);
    float inv3 = 1.f / fmaxf(s3, 1e-20f);

    int hl = lane >> 3;
    float m_h  = (hl == 0) ? m0  : (hl == 1) ? m1  : (hl == 2) ? m2  : m3;
    float i_h  = (hl == 0) ? inv0 : (hl == 1) ? inv1 : (hl == 2) ? inv2 : inv3;
    float er_h = (hl == 0) ? erv.x : (hl == 1) ? erv.y : (hl == 2) ? erv.z : erv.w;

    // pass 2: weighted gather-accumulate, 4 dims per lane
    float4 acc = make_float4(0.f, 0.f, 0.f, 0.f);
    const float4* featv = (const float4*)feat;
    for (int j = beg; j < end; j++) {
        int e = g_perm[j];
        int s = srcIdx[e];
        float a = 0.f;
        if ((lane & 7) == 0) {
            float v = el[(size_t)s * 4 + hl] + er_h;
            v = v > 0.f ? v : 0.2f * v;
            a = __expf(v - m_h) * i_h * ew[e];
        }
        a = __shfl_sync(FULL, a, lane & 24);
        float4 f = featv[(size_t)s * 32 + lane];
        acc.x = fmaf(a, f.x, acc.x);
        acc.y = fmaf(a, f.y, acc.y);
        acc.z = fmaf(a, f.z, acc.z);
        acc.w = fmaf(a, f.w, acc.w);
    }

    float4 b = ((const float4*)bias)[lane];
    float4 o;
    o.x = acc.x + b.x; o.x = o.x > 0.f ? o.x : expm1f(o.x);
    o.y = acc.y + b.y; o.y = o.y > 0.f ? o.y : expm1f(o.y);
    o.z = acc.z + b.z; o.z = o.z > 0.f ? o.z : expm1f(o.z);
    o.w = acc.w + b.w; o.w = o.w > 0.f ? o.w : expm1f(o.w);
    ((float4*)out)[(size_t)node * 32 + lane] = o;
}

// ---------------- launcher ----------------
extern "C" void kernel_launch(void* const* d_in, const int* in_sizes, int n_in,
                              void* d_out, int out_size) {
    const float* in_feat = (const float*)d_in[0];
    const float* ew      = (const float*)d_in[1];
    const int*   src     = (const int*)d_in[2];
    const int*   dst     = (const int*)d_in[3];
    const float* W0      = (const float*)d_in[4];
    const float* al0     = (const float*)d_in[5];
    const float* ar0     = (const float*)d_in[6];
    const float* b0      = (const float*)d_in[7];
    const float* W1      = (const float*)d_in[8];
    const float* al1     = (const float*)d_in[9];
    const float* ar1     = (const float*)d_in[10];
    const float* b1      = (const float*)d_in[11];
    float* out = (float*)d_out;

    int N = in_sizes[0] / 128;
    int E = in_sizes[1];

    float* feat_p; float* h_p; float* el_p; float* er_p;
    // device globals are referenced directly inside kernels; only feat/el/er/h
    // are passed as parameters for __restrict__ benefit.
    // (symbols resolved at compile time)
    cudaGetSymbolAddress((void**)&feat_p, g_feat);
    cudaGetSymbolAddress((void**)&h_p,    g_h);
    cudaGetSymbolAddress((void**)&el_p,   g_el);
    cudaGetSymbolAddress((void**)&er_p,   g_er);

    // CSR build (graph shared by both layers)
    zero_deg_kernel<<<(N + 255) / 256, 256>>>(N);
    hist_kernel<<<(E + 255) / 256, 256>>>(dst, E);
    scan_kernel<<<1, 1024>>>(N);
    scatter_kernel<<<(E + 255) / 256, 256>>>(dst, E);

    int gemm_blocks = (N + 31) / 32;
    int agg_blocks  = (N + 7) / 8;

    // layer 0
    gemm_attn_kernel<<<gemm_blocks, 256>>>(in_feat, W0, al0, ar0, feat_p, el_p, er_p, N);
    aggregate_kernel<<<agg_blocks, 256>>>(feat_p, el_p, er_p, src, ew, b0, h_p, N);
    // layer 1
    gemm_attn_kernel<<<gemm_blocks, 256>>>(h_p, W1, al1, ar1, feat_p, el_p, er_p, N);
    aggregate_kernel<<<agg_blocks, 256>>>(feat_p, el_p, er_p, src, ew, b1, out, N);
}

// round 5
// speedup vs baseline: 1.3343x; 1.3343x over previous
#include <cuda_runtime.h>
#include <math.h>

#define N_NODES 100000
#define N_EDGES 3200000
#define FULL 0xffffffffu

// ---------------- static scratch (no allocation allowed) ----------------
__device__ float g_feat[N_NODES * 128];   // per-layer transformed features
__device__ float g_h[N_NODES * 128];      // layer-1 output
__device__ float g_el[N_NODES * 4];
__device__ float g_er[N_NODES * 4];
__device__ int   g_deg[N_NODES];
__device__ int   g_off[N_NODES + 1];
__device__ int   g_cur[N_NODES];
__device__ int   g_src_s[N_EDGES];        // src sorted by dst
__device__ float g_ew_s[N_EDGES];         // edge weight sorted by dst

// ---------------- CSR build ----------------
__global__ void zero_deg_kernel(int n) {
    int i = blockIdx.x * blockDim.x + threadIdx.x;
    if (i < n) g_deg[i] = 0;
}

__global__ void hist_kernel(const int* __restrict__ dst, int e) {
    int i = blockIdx.x * blockDim.x + threadIdx.x;
    if (i < e) atomicAdd(&g_deg[dst[i]], 1);
}

__global__ void scan_kernel(int n) {
    __shared__ int part[1024];
    int tid = threadIdx.x;
    int chunk = (n + 1023) / 1024;
    int b = tid * chunk;
    int e = min(b + chunk, n);
    int s = 0;
    for (int i = b; i < e; i++) s += g_deg[i];
    part[tid] = s;
    __syncthreads();
    for (int off = 1; off < 1024; off <<= 1) {
        int v = (tid >= off) ? part[tid - off] : 0;
        __syncthreads();
        part[tid] += v;
        __syncthreads();
    }
    int run = tid ? part[tid - 1] : 0;
    for (int i = b; i < e; i++) {
        g_off[i] = run;
        g_cur[i] = run;
        run += g_deg[i];
    }
    if (tid == 0) g_off[n] = part[1023];
}

// Scatter src + edge-weight directly into dst-sorted order (no perm array).
__global__ void scatter_kernel(const int* __restrict__ src,
                               const int* __restrict__ dst,
                               const float* __restrict__ ew, int e) {
    int i = blockIdx.x * blockDim.x + threadIdx.x;
    if (i < e) {
        int p = atomicAdd(&g_cur[dst[i]], 1);
        g_src_s[p] = src[i];
        g_ew_s[p]  = ew[i];
    }
}

// ---------------- GEMM + fused el/er ----------------
// Block = 256 threads = 8 warps; each warp computes 4 rows x 128 cols.
// Lane cg owns cols [cg*4, cg*4+3] (within head cg>>3). W rows stay L1-resident
// across CTAs on the same SM (L1 persists within a launch).
__global__ __launch_bounds__(256) void gemm_attn_kernel(
    const float* __restrict__ h, const float* __restrict__ W,
    const float* __restrict__ al, const float* __restrict__ ar,
    float* __restrict__ feat, float* __restrict__ el, float* __restrict__ er,
    int n)
{
    int warp = threadIdx.x >> 5;
    int cg   = threadIdx.x & 31;
    int row0 = (blockIdx.x * 8 + warp) * 4;
    if (row0 >= n) return;

    const float4* W4 = (const float4*)W;
    float acc[4][4];
    #pragma unroll
    for (int r = 0; r < 4; r++) { acc[r][0] = acc[r][1] = acc[r][2] = acc[r][3] = 0.f; }

    for (int k = 0; k < 128; k += 4) {
        float hb[4][4];
        #pragma unroll
        for (int r = 0; r < 4; r++) {
            float4 t = *(const float4*)(h + (size_t)(row0 + r) * 128 + k);
            hb[r][0] = t.x; hb[r][1] = t.y; hb[r][2] = t.z; hb[r][3] = t.w;
        }
        #pragma unroll
        for (int kk = 0; kk < 4; kk++) {
            float4 w = __ldg(&W4[(k + kk) * 32 + cg]);
            #pragma unroll
            for (int r = 0; r < 4; r++) {
                acc[r][0] = fmaf(hb[r][kk], w.x, acc[r][0]);
                acc[r][1] = fmaf(hb[r][kk], w.y, acc[r][1]);
                acc[r][2] = fmaf(hb[r][kk], w.z, acc[r][2]);
                acc[r][3] = fmaf(hb[r][kk], w.w, acc[r][3]);
            }
        }
    }

    float4 al4 = __ldg(&((const float4*)al)[cg]);
    float4 ar4 = __ldg(&((const float4*)ar)[cg]);

    #pragma unroll
    for (int r = 0; r < 4; r++) {
        float pl = acc[r][0] * al4.x + acc[r][1] * al4.y + acc[r][2] * al4.z + acc[r][3] * al4.w;
        float pr = acc[r][0] * ar4.x + acc[r][1] * ar4.y + acc[r][2] * ar4.z + acc[r][3] * ar4.w;
        #pragma unroll
        for (int off = 4; off; off >>= 1) {
            pl += __shfl_down_sync(FULL, pl, off);
            pr += __shfl_down_sync(FULL, pr, off);
        }
        if ((cg & 7) == 0) {
            int hl = cg >> 3;
            el[(size_t)(row0 + r) * 4 + hl] = pl;
            er[(size_t)(row0 + r) * 4 + hl] = pr;
        }
        float4 o;
        o.x = acc[r][0]; o.y = acc[r][1]; o.z = acc[r][2]; o.w = acc[r][3];
        ((float4*)feat)[(size_t)(row0 + r) * 32 + cg] = o;
    }
}

// ---------------- per-node softmax + aggregation ----------------
__device__ __forceinline__ void merge_ms(float& m, float& s, int off) {
    float om = __shfl_down_sync(FULL, m, off);
    float os = __shfl_down_sync(FULL, s, off);
    float nm = fmaxf(m, om);
    // fmaxf(NaN, -88) == -88 handles the (-inf - -inf) case safely
    s = s * __expf(fmaxf(m - nm, -88.f)) + os * __expf(fmaxf(om - nm, -88.f));
    m = nm;
}

// One warp per destination node.
// Pass 1: online softmax stats per head, lane-strided over sorted edges.
// Pass 2: 8-edge groups. Lane (hg*8+t) computes the coefficient of edge t for
// head hg (all 32 lanes active), then an unrolled loop over the 8 edges issues
// 8 independent 512B feature gathers (MLP=8) with register accumulation.
__global__ __launch_bounds__(256) void aggregate_kernel(
    const float* __restrict__ feat, const float* __restrict__ el,
    const float* __restrict__ er, const float* __restrict__ bias,
    float* __restrict__ out, int n)
{
    int warp = threadIdx.x >> 5;
    int lane = threadIdx.x & 31;
    int node = blockIdx.x * 8 + warp;
    if (node >= n) return;

    int beg = g_off[node];
    int end = g_off[node + 1];

    float4 erv = *(const float4*)(er + (size_t)node * 4);

    // ---- pass 1: online softmax stats per head ----
    float m0 = -INFINITY, m1 = -INFINITY, m2 = -INFINITY, m3 = -INFINITY;
    float s0 = 0.f, s1 = 0.f, s2 = 0.f, s3 = 0.f;
    for (int j = beg + lane; j < end; j += 32) {
        int s = g_src_s[j];
        float4 elv = *(const float4*)(el + (size_t)s * 4);
        float v;
        v = elv.x + erv.x; v = v > 0.f ? v : 0.2f * v;
        if (v <= m0) s0 += __expf(v - m0); else { s0 = s0 * __expf(m0 - v) + 1.f; m0 = v; }
        v = elv.y + erv.y; v = v > 0.f ? v : 0.2f * v;
        if (v <= m1) s1 += __expf(v - m1); else { s1 = s1 * __expf(m1 - v) + 1.f; m1 = v; }
        v = elv.z + erv.z; v = v > 0.f ? v : 0.2f * v;
        if (v <= m2) s2 += __expf(v - m2); else { s2 = s2 * __expf(m2 - v) + 1.f; m2 = v; }
        v = elv.w + erv.w; v = v > 0.f ? v : 0.2f * v;
        if (v <= m3) s3 += __expf(v - m3); else { s3 = s3 * __expf(m3 - v) + 1.f; m3 = v; }
    }
    #pragma unroll
    for (int off = 16; off; off >>= 1) {
        merge_ms(m0, s0, off);
        merge_ms(m1, s1, off);
        merge_ms(m2, s2, off);
        merge_ms(m3, s3, off);
    }
    m0 = __shfl_sync(FULL, m0, 0); s0 = __shfl_sync(FULL, s0, 0);
    m1 = __shfl_sync(FULL, m1, 0); s1 = __shfl_sync(FULL, s1, 0);
    m2 = __shfl_sync(FULL, m2, 0); s2 = __shfl_sync(FULL, s2, 0);
    m3 = __shfl_sync(FULL, m3, 0); s3 = __shfl_sync(FULL, s3, 0);

    int hl   = lane >> 3;     // my head
    int sub  = lane & 7;      // my edge slot within a group of 8
    int hbase = lane & 24;    // first lane of my head group

    float m_h  = (hl == 0) ? m0 : (hl == 1) ? m1 : (hl == 2) ? m2 : m3;
    float s_h  = (hl == 0) ? s0 : (hl == 1) ? s1 : (hl == 2) ? s2 : s3;
    float i_h  = 1.f / fmaxf(s_h, 1e-20f);
    float er_h = (hl == 0) ? erv.x : (hl == 1) ? erv.y : (hl == 2) ? erv.z : erv.w;

    // ---- pass 2: 8-edge-grouped weighted gather-accumulate ----
    float4 acc = make_float4(0.f, 0.f, 0.f, 0.f);
    const float4* featv = (const float4*)feat;

    int j = beg;
    for (; j + 8 <= end; j += 8) {
        int jj = j + sub;
        int s  = g_src_s[jj];
        float v = __ldg(&el[(size_t)s * 4 + hl]) + er_h;
        v = v > 0.f ? v : 0.2f * v;
        float a = __expf(v - m_h) * i_h * __ldg(&g_ew_s[jj]);
        #pragma unroll
        for (int t = 0; t < 8; t++) {
            int   ss = __shfl_sync(FULL, s, t);
            float at = __shfl_sync(FULL, a, hbase | t);
            float4 f = featv[(size_t)ss * 32 + lane];
            acc.x = fmaf(at, f.x, acc.x);
            acc.y = fmaf(at, f.y, acc.y);
            acc.z = fmaf(at, f.z, acc.z);
            acc.w = fmaf(at, f.w, acc.w);
        }
    }
    int rem = end - j;
    if (rem > 0) {
        int s = 0;
        float a = 0.f;
        if (sub < rem) {
            int jj = j + sub;
            s = g_src_s[jj];
            float v = __ldg(&el[(size_t)s * 4 + hl]) + er_h;
            v = v > 0.f ? v : 0.2f * v;
            a = __expf(v - m_h) * i_h * __ldg(&g_ew_s[jj]);
        }
        for (int t = 0; t < rem; t++) {
            int   ss = __shfl_sync(FULL, s, t);
            float at = __shfl_sync(FULL, a, hbase | t);
            float4 f = featv[(size_t)ss * 32 + lane];
            acc.x = fmaf(at, f.x, acc.x);
            acc.y = fmaf(at, f.y, acc.y);
            acc.z = fmaf(at, f.z, acc.z);
            acc.w = fmaf(at, f.w, acc.w);
        }
    }

    float4 b = ((const float4*)bias)[lane];
    float4 o;
    o.x = acc.x + b.x; o.x = o.x > 0.f ? o.x : expm1f(o.x);
    o.y = acc.y + b.y; o.y = o.y > 0.f ? o.y : expm1f(o.y);
    o.z = acc.z + b.z; o.z = o.z > 0.f ? o.z : expm1f(o.z);
    o.w = acc.w + b.w; o.w = o.w > 0.f ? o.w : expm1f(o.w);
    ((float4*)out)[(size_t)node * 32 + lane] = o;
}

// ---------------- launcher ----------------
extern "C" void kernel_launch(void* const* d_in, const int* in_sizes, int n_in,
                              void* d_out, int out_size) {
    const float* in_feat = (const float*)d_in[0];
    const float* ew      = (const float*)d_in[1];
    const int*   src     = (const int*)d_in[2];
    const int*   dst     = (const int*)d_in[3];
    const float* W0      = (const float*)d_in[4];
    const float* al0     = (const float*)d_in[5];
    const float* ar0     = (const float*)d_in[6];
    const float* b0      = (const float*)d_in[7];
    const float* W1      = (const float*)d_in[8];
    const float* al1     = (const float*)d_in[9];
    const float* ar1     = (const float*)d_in[10];
    const float* b1      = (const float*)d_in[11];
    float* out = (float*)d_out;

    int N = in_sizes[0] / 128;
    int E = in_sizes[1];

    float* feat_p; float* h_p; float* el_p; float* er_p;
    cudaGetSymbolAddress((void**)&feat_p, g_feat);
    cudaGetSymbolAddress((void**)&h_p,    g_h);
    cudaGetSymbolAddress((void**)&el_p,   g_el);
    cudaGetSymbolAddress((void**)&er_p,   g_er);

    // CSR build (graph shared by both layers); scatter also pre-sorts src/ew
    zero_deg_kernel<<<(N + 255) / 256, 256>>>(N);
    hist_kernel<<<(E + 255) / 256, 256>>>(dst, E);
    scan_kernel<<<1, 1024>>>(N);
    scatter_kernel<<<(E + 255) / 256, 256>>>(src, dst, ew, E);

    int gemm_blocks = (N + 31) / 32;
    int agg_blocks  = (N + 7) / 8;

    // layer 0
    gemm_attn_kernel<<<gemm_blocks, 256>>>(in_feat, W0, al0, ar0, feat_p, el_p, er_p, N);
    aggregate_kernel<<<agg_blocks, 256>>>(feat_p, el_p, er_p, b0, h_p, N);
    // layer 1
    gemm_attn_kernel<<<gemm_blocks, 256>>>(h_p, W1, al1, ar1, feat_p, el_p, er_p, N);
    aggregate_kernel<<<agg_blocks, 256>>>(feat_p, el_p, er_p, b1, out, N);
}

// round 6
// speedup vs baseline: 1.5187x; 1.1383x over previous
#include <cuda_runtime.h>
#include <math.h>

#define N_NODES 100000
#define N_EDGES 3200000
#define FULL 0xffffffffu

// ---------------- static scratch (no allocation allowed) ----------------
__device__ float g_feat[N_NODES * 128];   // per-layer transformed features
__device__ float g_h[N_NODES * 128];      // layer-1 output
__device__ float g_el[N_NODES * 4];
__device__ float g_er[N_NODES * 4];
__device__ int   g_deg[N_NODES];
__device__ int   g_off[N_NODES + 1];
__device__ int   g_cur[N_NODES];
__device__ int2  g_edge_s[N_EDGES];       // {src, ew-bits} sorted by dst

// ---------------- CSR build ----------------
__global__ void zero_deg_kernel(int n) {
    int i = blockIdx.x * blockDim.x + threadIdx.x;
    if (i < n) g_deg[i] = 0;
}

__global__ void hist_kernel(const int* __restrict__ dst, int e) {
    int i = blockIdx.x * blockDim.x + threadIdx.x;
    if (i < e) atomicAdd(&g_deg[dst[i]], 1);
}

__global__ void scan_kernel(int n) {
    __shared__ int part[1024];
    int tid = threadIdx.x;
    int chunk = (n + 1023) / 1024;
    int b = tid * chunk;
    int e = min(b + chunk, n);
    int s = 0;
    for (int i = b; i < e; i++) s += g_deg[i];
    part[tid] = s;
    __syncthreads();
    for (int off = 1; off < 1024; off <<= 1) {
        int v = (tid >= off) ? part[tid - off] : 0;
        __syncthreads();
        part[tid] += v;
        __syncthreads();
    }
    int run = tid ? part[tid - 1] : 0;
    for (int i = b; i < e; i++) {
        g_off[i] = run;
        g_cur[i] = run;
        run += g_deg[i];
    }
    if (tid == 0) g_off[n] = part[1023];
}

// Scatter {src, ew} as one packed 8B record into dst-sorted order.
__global__ void scatter_kernel(const int* __restrict__ src,
                               const int* __restrict__ dst,
                               const float* __restrict__ ew, int e) {
    int i = blockIdx.x * blockDim.x + threadIdx.x;
    if (i < e) {
        int p = atomicAdd(&g_cur[dst[i]], 1);
        g_edge_s[p] = make_int2(src[i], __float_as_int(ew[i]));
    }
}

// ---------------- GEMM + fused el/er ----------------
// Block = 256 threads = 8 warps; each warp computes 4 rows x 128 cols.
// Lane cg owns cols [cg*4, cg*4+3] (within head cg>>3). W stays L1-resident.
__global__ __launch_bounds__(256) void gemm_attn_kernel(
    const float* __restrict__ h, const float* __restrict__ W,
    const float* __restrict__ al, const float* __restrict__ ar,
    float* __restrict__ feat, float* __restrict__ el, float* __restrict__ er,
    int n)
{
    int warp = threadIdx.x >> 5;
    int cg   = threadIdx.x & 31;
    int row0 = (blockIdx.x * 8 + warp) * 4;
    if (row0 >= n) return;

    const float4* W4 = (const float4*)W;
    float acc[4][4];
    #pragma unroll
    for (int r = 0; r < 4; r++) { acc[r][0] = acc[r][1] = acc[r][2] = acc[r][3] = 0.f; }

    for (int k = 0; k < 128; k += 4) {
        float hb[4][4];
        #pragma unroll
        for (int r = 0; r < 4; r++) {
            float4 t = *(const float4*)(h + (size_t)(row0 + r) * 128 + k);
            hb[r][0] = t.x; hb[r][1] = t.y; hb[r][2] = t.z; hb[r][3] = t.w;
        }
        #pragma unroll
        for (int kk = 0; kk < 4; kk++) {
            float4 w = __ldg(&W4[(k + kk) * 32 + cg]);
            #pragma unroll
            for (int r = 0; r < 4; r++) {
                acc[r][0] = fmaf(hb[r][kk], w.x, acc[r][0]);
                acc[r][1] = fmaf(hb[r][kk], w.y, acc[r][1]);
                acc[r][2] = fmaf(hb[r][kk], w.z, acc[r][2]);
                acc[r][3] = fmaf(hb[r][kk], w.w, acc[r][3]);
            }
        }
    }

    float4 al4 = __ldg(&((const float4*)al)[cg]);
    float4 ar4 = __ldg(&((const float4*)ar)[cg]);

    #pragma unroll
    for (int r = 0; r < 4; r++) {
        float pl = acc[r][0] * al4.x + acc[r][1] * al4.y + acc[r][2] * al4.z + acc[r][3] * al4.w;
        float pr = acc[r][0] * ar4.x + acc[r][1] * ar4.y + acc[r][2] * ar4.z + acc[r][3] * ar4.w;
        #pragma unroll
        for (int off = 4; off; off >>= 1) {
            pl += __shfl_down_sync(FULL, pl, off);
            pr += __shfl_down_sync(FULL, pr, off);
        }
        if ((cg & 7) == 0) {
            int hl = cg >> 3;
            el[(size_t)(row0 + r) * 4 + hl] = pl;
            er[(size_t)(row0 + r) * 4 + hl] = pr;
        }
        float4 o;
        o.x = acc[r][0]; o.y = acc[r][1]; o.z = acc[r][2]; o.w = acc[r][3];
        ((float4*)feat)[(size_t)(row0 + r) * 32 + cg] = o;
    }
}

// ---------------- fused softmax + aggregation (single edge pass) ----------------
// One warp per destination node. Max-subtraction dropped (algebraically
// identical; logits are O(1) here, clamp at 40 as insurance). Each 8-edge
// group: lane (hg*8+t) computes exp coefficient of edge t for head hg and
// accumulates the per-head denominator; then 8 independent 512B feature
// gathers FMA into register accumulators. Normalize + bias + ELU in epilogue.
__global__ __launch_bounds__(256) void aggregate_kernel(
    const float* __restrict__ feat, const float* __restrict__ el,
    const float* __restrict__ er, const float* __restrict__ bias,
    float* __restrict__ out, int n)
{
    int warp = threadIdx.x >> 5;
    int lane = threadIdx.x & 31;
    int node = blockIdx.x * 8 + warp;
    if (node >= n) return;

    int beg = g_off[node];
    int end = g_off[node + 1];

    int hl    = lane >> 3;     // my head
    int sub   = lane & 7;      // my edge slot within a group of 8
    int hbase = lane & 24;     // first lane of my head group

    float er_h = __ldg(&er[(size_t)node * 4 + hl]);

    float  se  = 0.f;          // partial softmax denominator (my head, my slots)
    float4 acc = make_float4(0.f, 0.f, 0.f, 0.f);
    const float4* featv = (const float4*)feat;
    const int2*   edges = g_edge_s;

    int j = beg;
    for (; j + 8 <= end; j += 8) {
        int2  ed = edges[j + sub];
        int   s  = ed.x;
        float w  = __int_as_float(ed.y);
        float v  = __ldg(&el[(size_t)s * 4 + hl]) + er_h;
        v = v > 0.f ? v : 0.2f * v;
        v = fminf(v, 40.f);
        float ex = __expf(v);
        se += ex;
        float a = ex * w;
        #pragma unroll
        for (int t = 0; t < 8; t++) {
            int   ss = __shfl_sync(FULL, s, t);
            float at = __shfl_sync(FULL, a, hbase | t);
            float4 f = featv[(size_t)ss * 32 + lane];
            acc.x = fmaf(at, f.x, acc.x);
            acc.y = fmaf(at, f.y, acc.y);
            acc.z = fmaf(at, f.z, acc.z);
            acc.w = fmaf(at, f.w, acc.w);
        }
    }
    int rem = end - j;
    if (rem > 0) {
        int s = 0;
        float a = 0.f;
        if (sub < rem) {
            int2  ed = edges[j + sub];
            s = ed.x;
            float w = __int_as_float(ed.y);
            float v = __ldg(&el[(size_t)s * 4 + hl]) + er_h;
            v = v > 0.f ? v : 0.2f * v;
            v = fminf(v, 40.f);
            float ex = __expf(v);
            se += ex;
            a = ex * w;
        }
        for (int t = 0; t < rem; t++) {
            int   ss = __shfl_sync(FULL, s, t);
            float at = __shfl_sync(FULL, a, hbase | t);
            float4 f = featv[(size_t)ss * 32 + lane];
            acc.x = fmaf(at, f.x, acc.x);
            acc.y = fmaf(at, f.y, acc.y);
            acc.z = fmaf(at, f.z, acc.z);
            acc.w = fmaf(at, f.w, acc.w);
        }
    }

    // reduce denominator across the 8 lanes of my head group
    se += __shfl_xor_sync(FULL, se, 1);
    se += __shfl_xor_sync(FULL, se, 2);
    se += __shfl_xor_sync(FULL, se, 4);
    float i_h = 1.f / fmaxf(se, 1e-20f);

    float4 b = ((const float4*)bias)[lane];
    float4 o;
    o.x = fmaf(acc.x, i_h, b.x); o.x = o.x > 0.f ? o.x : expm1f(o.x);
    o.y = fmaf(acc.y, i_h, b.y); o.y = o.y > 0.f ? o.y : expm1f(o.y);
    o.z = fmaf(acc.z, i_h, b.z); o.z = o.z > 0.f ? o.z : expm1f(o.z);
    o.w = fmaf(acc.w, i_h, b.w); o.w = o.w > 0.f ? o.w : expm1f(o.w);
    ((float4*)out)[(size_t)node * 32 + lane] = o;
}

// ---------------- launcher ----------------
extern "C" void kernel_launch(void* const* d_in, const int* in_sizes, int n_in,
                              void* d_out, int out_size) {
    const float* in_feat = (const float*)d_in[0];
    const float* ew      = (const float*)d_in[1];
    const int*   src     = (const int*)d_in[2];
    const int*   dst     = (const int*)d_in[3];
    const float* W0      = (const float*)d_in[4];
    const float* al0     = (const float*)d_in[5];
    const float* ar0     = (const float*)d_in[6];
    const float* b0      = (const float*)d_in[7];
    const float* W1      = (const float*)d_in[8];
    const float* al1     = (const float*)d_in[9];
    const float* ar1     = (const float*)d_in[10];
    const float* b1      = (const float*)d_in[11];
    float* out = (float*)d_out;

    int N = in_sizes[0] / 128;
    int E = in_sizes[1];

    float* feat_p; float* h_p; float* el_p; float* er_p;
    cudaGetSymbolAddress((void**)&feat_p, g_feat);
    cudaGetSymbolAddress((void**)&h_p,    g_h);
    cudaGetSymbolAddress((void**)&el_p,   g_el);
    cudaGetSymbolAddress((void**)&er_p,   g_er);

    // CSR build (graph shared by both layers); scatter pre-sorts {src, ew}
    zero_deg_kernel<<<(N + 255) / 256, 256>>>(N);
    hist_kernel<<<(E + 255) / 256, 256>>>(dst, E);
    scan_kernel<<<1, 1024>>>(N);
    scatter_kernel<<<(E + 255) / 256, 256>>>(src, dst, ew, E);

    int gemm_blocks = (N + 31) / 32;
    int agg_blocks  = (N + 7) / 8;

    // layer 0
    gemm_attn_kernel<<<gemm_blocks, 256>>>(in_feat, W0, al0, ar0, feat_p, el_p, er_p, N);
    aggregate_kernel<<<agg_blocks, 256>>>(feat_p, el_p, er_p, b0, h_p, N);
    // layer 1
    gemm_attn_kernel<<<gemm_blocks, 256>>>(h_p, W1, al1, ar1, feat_p, el_p, er_p, N);
    aggregate_kernel<<<agg_blocks, 256>>>(feat_p, el_p, er_p, b1, out, N);
}

// round 8
// speedup vs baseline: 1.6055x; 1.0571x over previous
#include <cuda_runtime.h>
#include <cuda_fp16.h>
#include <math.h>

#define N_NODES 100000
#define N_EDGES 3200000
#define FULL 0xffffffffu

// ---------------- static scratch (no allocation allowed) ----------------
__device__ unsigned int g_featH[N_NODES * 64]; // transformed feats as half (128 halves = 64 u32)
__device__ float g_h[N_NODES * 128];           // layer-1 output (fp32)
__device__ float g_el[N_NODES * 4];
__device__ float g_er[N_NODES * 4];
__device__ int   g_deg[N_NODES];
__device__ int   g_off[N_NODES + 1];
__device__ int   g_cur[N_NODES];
__device__ int2  g_edge_s[N_EDGES];            // {src, ew-bits} sorted by dst

// ---------------- CSR build ----------------
__global__ void zero_deg_kernel(int n) {
    int i = blockIdx.x * blockDim.x + threadIdx.x;
    if (i < n) g_deg[i] = 0;
}

__global__ void hist_kernel(const int* __restrict__ dst, int e) {
    int i = blockIdx.x * blockDim.x + threadIdx.x;
    if (i < e) atomicAdd(&g_deg[dst[i]], 1);
}

__global__ void scan_kernel(int n) {
    __shared__ int part[1024];
    int tid = threadIdx.x;
    int chunk = (n + 1023) / 1024;
    int b = tid * chunk;
    int e = min(b + chunk, n);
    int s = 0;
    for (int i = b; i < e; i++) s += g_deg[i];
    part[tid] = s;
    __syncthreads();
    for (int off = 1; off < 1024; off <<= 1) {
        int v = (tid >= off) ? part[tid - off] : 0;
        __syncthreads();
        part[tid] += v;
        __syncthreads();
    }
    int run = tid ? part[tid - 1] : 0;
    for (int i = b; i < e; i++) {
        g_off[i] = run;
        g_cur[i] = run;
        run += g_deg[i];
    }
    if (tid == 0) g_off[n] = part[1023];
}

// Scatter {src, ew} as one packed 8B record into dst-sorted order.
__global__ void scatter_kernel(const int* __restrict__ src,
                               const int* __restrict__ dst,
                               const float* __restrict__ ew, int e) {
    int i = blockIdx.x * blockDim.x + threadIdx.x;
    if (i < e) {
        int p = atomicAdd(&g_cur[dst[i]], 1);
        g_edge_s[p] = make_int2(src[i], __float_as_int(ew[i]));
    }
}

// ---------------- GEMM + fused el/er ----------------
// Block = 256 threads = 8 warps; each warp computes 4 rows x 128 cols in fp32.
// el/er come from the exact fp32 accumulators; feat is stored as half (only
// the softmax-weighted message path consumes it).
__global__ __launch_bounds__(256) void gemm_attn_kernel(
    const float* __restrict__ h, const float* __restrict__ W,
    const float* __restrict__ al, const float* __restrict__ ar,
    unsigned int* __restrict__ featH, float* __restrict__ el,
    float* __restrict__ er, int n)
{
    int warp = threadIdx.x >> 5;
    int cg   = threadIdx.x & 31;
    int row0 = (blockIdx.x * 8 + warp) * 4;
    if (row0 >= n) return;

    const float4* W4 = (const float4*)W;
    float acc[4][4];
    #pragma unroll
    for (int r = 0; r < 4; r++) { acc[r][0] = acc[r][1] = acc[r][2] = acc[r][3] = 0.f; }

    for (int k = 0; k < 128; k += 4) {
        float hb[4][4];
        #pragma unroll
        for (int r = 0; r < 4; r++) {
            float4 t = *(const float4*)(h + (size_t)(row0 + r) * 128 + k);
            hb[r][0] = t.x; hb[r][1] = t.y; hb[r][2] = t.z; hb[r][3] = t.w;
        }
        #pragma unroll
        for (int kk = 0; kk < 4; kk++) {
            float4 w = __ldg(&W4[(k + kk) * 32 + cg]);
            #pragma unroll
            for (int r = 0; r < 4; r++) {
                acc[r][0] = fmaf(hb[r][kk], w.x, acc[r][0]);
                acc[r][1] = fmaf(hb[r][kk], w.y, acc[r][1]);
                acc[r][2] = fmaf(hb[r][kk], w.z, acc[r][2]);
                acc[r][3] = fmaf(hb[r][kk], w.w, acc[r][3]);
            }
        }
    }

    float4 al4 = __ldg(&((const float4*)al)[cg]);
    float4 ar4 = __ldg(&((const float4*)ar)[cg]);

    #pragma unroll
    for (int r = 0; r < 4; r++) {
        float pl = acc[r][0] * al4.x + acc[r][1] * al4.y + acc[r][2] * al4.z + acc[r][3] * al4.w;
        float pr = acc[r][0] * ar4.x + acc[r][1] * ar4.y + acc[r][2] * ar4.z + acc[r][3] * ar4.w;
        #pragma unroll
        for (int off = 4; off; off >>= 1) {
            pl += __shfl_down_sync(FULL, pl, off);
            pr += __shfl_down_sync(FULL, pr, off);
        }
        if ((cg & 7) == 0) {
            int hl = cg >> 3;
            el[(size_t)(row0 + r) * 4 + hl] = pl;
            er[(size_t)(row0 + r) * 4 + hl] = pr;
        }
        __half2 h01 = __floats2half2_rn(acc[r][0], acc[r][1]);
        __half2 h23 = __floats2half2_rn(acc[r][2], acc[r][3]);
        uint2 o;
        o.x = *(unsigned int*)&h01;
        o.y = *(unsigned int*)&h23;
        ((uint2*)featH)[(size_t)(row0 + r) * 32 + cg] = o;
    }
}

// ---------------- fused softmax + aggregation (single edge pass) ----------------
// One warp per destination node. Per 32-edge block: one coalesced int2 load,
// 4 independent el gathers (MLP=4), then 4 groups of 8 independent 256B half
// feature gathers with fp32 register accumulation. Normalize+bias+ELU epilogue.
__global__ __launch_bounds__(256) void aggregate_kernel(
    const unsigned int* __restrict__ featH, const float* __restrict__ el,
    const float* __restrict__ er, const float* __restrict__ bias,
    float* __restrict__ out, int n)
{
    int warp = threadIdx.x >> 5;
    int lane = threadIdx.x & 31;
    int node = blockIdx.x * 8 + warp;
    if (node >= n) return;

    int beg = g_off[node];
    int end = g_off[node + 1];

    int hl    = lane >> 3;     // my head
    int sub   = lane & 7;      // my edge slot within a group of 8
    int hbase = lane & 24;     // first lane of my head group

    float er_h = __ldg(&er[(size_t)node * 4 + hl]);

    float  se  = 0.f;          // partial softmax denominator (my head, my slots)
    float4 acc = make_float4(0.f, 0.f, 0.f, 0.f);
    const uint2* featv = (const uint2*)featH;
    const int2*  edges = g_edge_s;

    for (int j = beg; j < end; j += 32) {
        int navail = end - j;
        // one coalesced metadata load covering up to 32 edges
        int2 ed = (j + lane < end) ? edges[j + lane] : make_int2(0, 0);

        int   sg[4];
        float wg[4];
        float elg[4];
        #pragma unroll
        for (int g = 0; g < 4; g++) {
            sg[g] = __shfl_sync(FULL, ed.x, g * 8 + sub);
            wg[g] = __int_as_float(__shfl_sync(FULL, ed.y, g * 8 + sub));
        }
        #pragma unroll
        for (int g = 0; g < 4; g++)   // 4 independent gathers, back-to-back
            elg[g] = __ldg(&el[(size_t)sg[g] * 4 + hl]);

        #pragma unroll
        for (int g = 0; g < 4; g++) {
            int base = g * 8;
            if (base >= navail) break;
            float v = elg[g] + er_h;
            v = v > 0.f ? v : 0.2f * v;
            v = fminf(v, 40.f);
            float ex = (base + sub < navail) ? __expf(v) : 0.f;
            se += ex;
            float a = ex * wg[g];
            int cnt = navail - base;
            if (cnt >= 8) {
                #pragma unroll
                for (int t = 0; t < 8; t++) {
                    int   ss = __shfl_sync(FULL, sg[g], t);
                    float at = __shfl_sync(FULL, a, hbase | t);
                    uint2 u  = featv[(size_t)ss * 32 + lane];
                    float2 f01 = __half22float2(*(__half2*)&u.x);
                    float2 f23 = __half22float2(*(__half2*)&u.y);
                    acc.x = fmaf(at, f01.x, acc.x);
                    acc.y = fmaf(at, f01.y, acc.y);
                    acc.z = fmaf(at, f23.x, acc.z);
                    acc.w = fmaf(at, f23.y, acc.w);
                }
            } else {
                for (int t = 0; t < cnt; t++) {
                    int   ss = __shfl_sync(FULL, sg[g], t);
                    float at = __shfl_sync(FULL, a, hbase | t);
                    uint2 u  = featv[(size_t)ss * 32 + lane];
                    float2 f01 = __half22float2(*(__half2*)&u.x);
                    float2 f23 = __half22float2(*(__half2*)&u.y);
                    acc.x = fmaf(at, f01.x, acc.x);
                    acc.y = fmaf(at, f01.y, acc.y);
                    acc.z = fmaf(at, f23.x, acc.z);
                    acc.w = fmaf(at, f23.y, acc.w);
                }
            }
        }
    }

    // reduce denominator across the 8 lanes of my head group
    se += __shfl_xor_sync(FULL, se, 1);
    se += __shfl_xor_sync(FULL, se, 2);
    se += __shfl_xor_sync(FULL, se, 4);
    float i_h = 1.f / fmaxf(se, 1e-20f);

    float4 b = ((const float4*)bias)[lane];
    float4 o;
    o.x = fmaf(acc.x, i_h, b.x); o.x = o.x > 0.f ? o.x : expm1f(o.x);
    o.y = fmaf(acc.y, i_h, b.y); o.y = o.y > 0.f ? o.y : expm1f(o.y);
    o.z = fmaf(acc.z, i_h, b.z); o.z = o.z > 0.f ? o.z : expm1f(o.z);
    o.w = fmaf(acc.w, i_h, b.w); o.w = o.w > 0.f ? o.w : expm1f(o.w);
    ((float4*)out)[(size_t)node * 32 + lane] = o;
}

// ---------------- launcher ----------------
extern "C" void kernel_launch(void* const* d_in, const int* in_sizes, int n_in,
                              void* d_out, int out_size) {
    const float* in_feat = (const float*)d_in[0];
    const float* ew      = (const float*)d_in[1];
    const int*   src     = (const int*)d_in[2];
    const int*   dst     = (const int*)d_in[3];
    const float* W0      = (const float*)d_in[4];
    const float* al0     = (const float*)d_in[5];
    const float* ar0     = (const float*)d_in[6];
    const float* b0      = (const float*)d_in[7];
    const float* W1      = (const float*)d_in[8];
    const float* al1     = (const float*)d_in[9];
    const float* ar1     = (const float*)d_in[10];
    const float* b1      = (const float*)d_in[11];
    float* out = (float*)d_out;

    int N = in_sizes[0] / 128;
    int E = in_sizes[1];

    unsigned int* featH_p; float* h_p; float* el_p; float* er_p;
    cudaGetSymbolAddress((void**)&featH_p, g_featH);
    cudaGetSymbolAddress((void**)&h_p,     g_h);
    cudaGetSymbolAddress((void**)&el_p,    g_el);
    cudaGetSymbolAddress((void**)&er_p,    g_er);

    // CSR build (graph shared by both layers); scatter pre-sorts {src, ew}
    zero_deg_kernel<<<(N + 255) / 256, 256>>>(N);
    hist_kernel<<<(E + 255) / 256, 256>>>(dst, E);
    scan_kernel<<<1, 1024>>>(N);
    scatter_kernel<<<(E + 255) / 256, 256>>>(src, dst, ew, E);

    int gemm_blocks = (N + 31) / 32;
    int agg_blocks  = (N + 7) / 8;

    // layer 0
    gemm_attn_kernel<<<gemm_blocks, 256>>>(in_feat, W0, al0, ar0, featH_p, el_p, er_p, N);
    aggregate_kernel<<<agg_blocks, 256>>>(featH_p, el_p, er_p, b0, h_p, N);
    // layer 1
    gemm_attn_kernel<<<gemm_blocks, 256>>>(h_p, W1, al1, ar1, featH_p, el_p, er_p, N);
    aggregate_kernel<<<agg_blocks, 256>>>(featH_p, el_p, er_p, b1, out, N);
}

// round 10
// speedup vs baseline: 1.9843x; 1.2359x over previous
#include <cuda_runtime.h>
#include <cuda_fp16.h>
#include <math.h>

#define N_NODES 100000
#define N_EDGES 3200000
#define FULL 0xffffffffu

// ---------------- static scratch (no allocation allowed) ----------------
__device__ unsigned int g_featH[N_NODES * 64]; // transformed feats, half-packed (128 halves = 64 u32)
__device__ unsigned int g_xH[N_NODES * 64];    // fp16 copy of layer-0 input
__device__ unsigned int g_hH[N_NODES * 64];    // fp16 layer-0 output (input to GEMM1)
__device__ __half g_WH[2][128 * 128];          // fp16 weights
__device__ float g_el[N_NODES * 4];
__device__ float g_er[N_NODES * 4];
__device__ int   g_deg[N_NODES];
__device__ int   g_off[N_NODES + 1];
__device__ int   g_cur[N_NODES];
__device__ int2  g_edge_s[N_EDGES];            // {src, ew-bits} sorted by dst

// ---------------- conversions ----------------
__global__ void cvt_feat_kernel(const float4* __restrict__ x, uint2* __restrict__ y, int n32) {
    int i = blockIdx.x * blockDim.x + threadIdx.x;
    if (i < n32) {
        float4 v = x[i];
        __half2 a = __floats2half2_rn(v.x, v.y);
        __half2 b = __floats2half2_rn(v.z, v.w);
        y[i] = make_uint2(*(unsigned int*)&a, *(unsigned int*)&b);
    }
}

__global__ void cvt_w_kernel(const float* __restrict__ W0, const float* __restrict__ W1) {
    int i = blockIdx.x * blockDim.x + threadIdx.x;
    if (i < 128 * 128) {
        g_WH[0][i] = __float2half_rn(W0[i]);
        g_WH[1][i] = __float2half_rn(W1[i]);
    }
}

// ---------------- CSR build ----------------
__global__ void hist_kernel(const int* __restrict__ dst, int e) {
    int i = blockIdx.x * blockDim.x + threadIdx.x;
    if (i < e) atomicAdd(&g_deg[dst[i]], 1);
}

__global__ void scan_kernel(int n) {
    __shared__ int part[1024];
    int tid = threadIdx.x;
    int chunk = (n + 1023) / 1024;
    int b = tid * chunk;
    int e = min(b + chunk, n);
    int s = 0;
    for (int i = b; i < e; i++) s += g_deg[i];
    part[tid] = s;
    __syncthreads();
    for (int off = 1; off < 1024; off <<= 1) {
        int v = (tid >= off) ? part[tid - off] : 0;
        __syncthreads();
        part[tid] += v;
        __syncthreads();
    }
    int run = tid ? part[tid - 1] : 0;
    for (int i = b; i < e; i++) {
        g_off[i] = run;
        g_cur[i] = run;
        run += g_deg[i];
    }
    if (tid == 0) g_off[n] = part[1023];
}

__global__ void scatter_kernel(const int* __restrict__ src,
                               const int* __restrict__ dst,
                               const float* __restrict__ ew, int e) {
    int i = blockIdx.x * blockDim.x + threadIdx.x;
    if (i < e) {
        int p = atomicAdd(&g_cur[dst[i]], 1);
        g_edge_s[p] = make_int2(src[i], __float_as_int(ew[i]));
    }
}

// ---------------- tensor-core GEMM + fused el/er ----------------
// 256 threads = 8 warps; CTA computes 128 rows x 128 cols. Warp: 16 rows.
// A (activations, fp16-packed) loaded directly from global in frag layout
// (L1-resident reuse). B = W staged in smem (XOR-swizzled), ldmatrix.x4.trans.
// Accumulate fp32; el/er from exact fp32 accumulators; feat stored half.
__global__ __launch_bounds__(256) void gemm_mma_kernel(
    const unsigned int* __restrict__ aH,   // [n*64] u32 (half2), row-major 128 halves/row
    const __half* __restrict__ wH,         // [128 k][128 n] row-major
    const float* __restrict__ al, const float* __restrict__ ar,
    unsigned int* __restrict__ featH, float* __restrict__ el,
    float* __restrict__ er, int n)
{
    __shared__ __align__(16) __half sW[128 * 128];
    int tid = threadIdx.x, lane = tid & 31, warp = tid >> 5;

    // stage W swizzled: 16B chunk (k, c) -> slot (k, c ^ (k&7))
    {
        const uint4* srcp = (const uint4*)wH;
        uint4* dstp = (uint4*)sW;
        #pragma unroll
        for (int i = tid; i < 2048; i += 256) {
            int k = i >> 4, c = i & 15;
            dstp[(k << 4) | (c ^ (k & 7))] = srcp[i];
        }
    }
    __syncthreads();

    int row0 = blockIdx.x * 128 + warp * 16;
    if (row0 >= n) return;   // n % 16 == 0, warp-granular guard

    float acc[64];
    #pragma unroll
    for (int i = 0; i < 64; i++) acc[i] = 0.f;

    int qr = lane >> 2;   // 0..7
    int qc = lane & 3;    // 0..3
    const unsigned int* aRow = aH + (size_t)(row0 + qr) * 64 + qc;

    unsigned int smemW = (unsigned int)__cvta_generic_to_shared(sW);
    int krow = (lane & 15);
    int cbase = (lane >> 4);

    #pragma unroll
    for (int ks = 0; ks < 8; ks++) {
        int k = ks * 16;
        // A frag: {(r,c),(r+8,c),(r,c+8),(r+8,c+8)} half2 each
        unsigned int A0 = aRow[k / 2];
        unsigned int A1 = aRow[8 * 64 + k / 2];
        unsigned int A2 = aRow[k / 2 + 4];
        unsigned int A3 = aRow[8 * 64 + k / 2 + 4];

        int kr = k + krow;
        unsigned int rowAddr = smemW + kr * 256;
        int ksw = kr & 7;

        #pragma unroll
        for (int np = 0; np < 8; np++) {
            unsigned int b0, b1, b2, b3;
            int cn = np * 2 + cbase;
            unsigned int addr = rowAddr + (((unsigned)(cn ^ ksw)) << 4);
            asm volatile("ldmatrix.sync.aligned.m8n8.x4.trans.shared.b16 {%0,%1,%2,%3}, [%4];\n"
                : "=r"(b0), "=r"(b1), "=r"(b2), "=r"(b3) : "r"(addr));
            float* c = acc + np * 8;
            asm volatile("mma.sync.aligned.m16n8k16.row.col.f32.f16.f16.f32 "
                "{%0,%1,%2,%3},{%4,%5,%6,%7},{%8,%9},{%0,%1,%2,%3};\n"
                : "+f"(c[0]), "+f"(c[1]), "+f"(c[2]), "+f"(c[3])
                : "r"(A0), "r"(A1), "r"(A2), "r"(A3), "r"(b0), "r"(b1));
            asm volatile("mma.sync.aligned.m16n8k16.row.col.f32.f16.f16.f32 "
                "{%0,%1,%2,%3},{%4,%5,%6,%7},{%8,%9},{%0,%1,%2,%3};\n"
                : "+f"(c[4]), "+f"(c[5]), "+f"(c[6]), "+f"(c[7])
                : "r"(A0), "r"(A1), "r"(A2), "r"(A3), "r"(b2), "r"(b3));
        }
    }

    // ---- el / er from fp32 accumulators ----
    // acc[np*8 + blk*4 + {0,1,2,3}]: {c0,c1} row (row0+qr) cols np*16+blk*8+qc*2+{0,1};
    //                                {c2,c3} row (row0+qr+8) same cols.
    int ra = row0 + qr, rb = ra + 8;
    #pragma unroll
    for (int hd = 0; hd < 4; hd++) {
        float sla = 0.f, slb = 0.f, sra = 0.f, srb = 0.f;
        #pragma unroll
        for (int t = 0; t < 4; t++) {
            int np = hd * 2 + (t >> 1), blk = t & 1;
            int c0 = np * 16 + blk * 8 + qc * 2;
            float a0v = __ldg(&al[c0]), a1v = __ldg(&al[c0 + 1]);
            float r0v = __ldg(&ar[c0]), r1v = __ldg(&ar[c0 + 1]);
            float* c = acc + np * 8 + blk * 4;
            sla += c[0] * a0v + c[1] * a1v;
            slb += c[2] * a0v + c[3] * a1v;
            sra += c[0] * r0v + c[1] * r1v;
            srb += c[2] * r0v + c[3] * r1v;
        }
        sla += __shfl_xor_sync(FULL, sla, 1); sla += __shfl_xor_sync(FULL, sla, 2);
        slb += __shfl_xor_sync(FULL, slb, 1); slb += __shfl_xor_sync(FULL, slb, 2);
        sra += __shfl_xor_sync(FULL, sra, 1); sra += __shfl_xor_sync(FULL, sra, 2);
        srb += __shfl_xor_sync(FULL, srb, 1); srb += __shfl_xor_sync(FULL, srb, 2);
        if (qc == 0) {
            el[(size_t)ra * 4 + hd] = sla;
            el[(size_t)rb * 4 + hd] = slb;
            er[(size_t)ra * 4 + hd] = sra;
            er[(size_t)rb * 4 + hd] = srb;
        }
    }

    // ---- store feat as half ----
    size_t ra64 = (size_t)ra * 64, rb64 = (size_t)rb * 64;
    #pragma unroll
    for (int np = 0; np < 8; np++) {
        #pragma unroll
        for (int blk = 0; blk < 2; blk++) {
            float* c = acc + np * 8 + blk * 4;
            __half2 ha = __floats2half2_rn(c[0], c[1]);
            __half2 hb = __floats2half2_rn(c[2], c[3]);
            int cu = np * 8 + blk * 4 + qc;   // u32 col index
            featH[ra64 + cu] = *(unsigned int*)&ha;
            featH[rb64 + cu] = *(unsigned int*)&hb;
        }
    }
}

// ---------------- fused softmax + aggregation (single edge pass) ----------------
__global__ __launch_bounds__(256) void aggregate_kernel(
    const unsigned int* __restrict__ featH, const float* __restrict__ el,
    const float* __restrict__ er, const float* __restrict__ bias,
    float* __restrict__ outF, unsigned int* __restrict__ outH,
    int writeHalf, int n)
{
    int warp = threadIdx.x >> 5;
    int lane = threadIdx.x & 31;
    int node = blockIdx.x * 8 + warp;
    if (node >= n) return;

    int beg = g_off[node];
    int end = g_off[node + 1];

    int hl    = lane >> 3;
    int sub   = lane & 7;
    int hbase = lane & 24;

    float er_h = __ldg(&er[(size_t)node * 4 + hl]);

    float  se  = 0.f;
    float4 acc = make_float4(0.f, 0.f, 0.f, 0.f);
    const uint2* featv = (const uint2*)featH;
    const int2*  edges = g_edge_s;

    for (int j = beg; j < end; j += 32) {
        int navail = end - j;
        int2 ed = (j + lane < end) ? edges[j + lane] : make_int2(0, 0);

        int   sg[4];
        float wg[4];
        float elg[4];
        #pragma unroll
        for (int g = 0; g < 4; g++) {
            sg[g] = __shfl_sync(FULL, ed.x, g * 8 + sub);
            wg[g] = __int_as_float(__shfl_sync(FULL, ed.y, g * 8 + sub));
        }
        #pragma unroll
        for (int g = 0; g < 4; g++)
            elg[g] = __ldg(&el[(size_t)sg[g] * 4 + hl]);

        #pragma unroll
        for (int g = 0; g < 4; g++) {
            int base = g * 8;
            if (base >= navail) break;
            float v = elg[g] + er_h;
            v = v > 0.f ? v : 0.2f * v;
            v = fminf(v, 40.f);
            float ex = (base + sub < navail) ? __expf(v) : 0.f;
            se += ex;
            float a = ex * wg[g];
            int cnt = navail - base;
            if (cnt >= 8) {
                #pragma unroll
                for (int t = 0; t < 8; t++) {
                    int   ss = __shfl_sync(FULL, sg[g], t);
                    float at = __shfl_sync(FULL, a, hbase | t);
                    uint2 u  = featv[(size_t)ss * 32 + lane];
                    float2 f01 = __half22float2(*(__half2*)&u.x);
                    float2 f23 = __half22float2(*(__half2*)&u.y);
                    acc.x = fmaf(at, f01.x, acc.x);
                    acc.y = fmaf(at, f01.y, acc.y);
                    acc.z = fmaf(at, f23.x, acc.z);
                    acc.w = fmaf(at, f23.y, acc.w);
                }
            } else {
                for (int t = 0; t < cnt; t++) {
                    int   ss = __shfl_sync(FULL, sg[g], t);
                    float at = __shfl_sync(FULL, a, hbase | t);
                    uint2 u  = featv[(size_t)ss * 32 + lane];
                    float2 f01 = __half22float2(*(__half2*)&u.x);
                    float2 f23 = __half22float2(*(__half2*)&u.y);
                    acc.x = fmaf(at, f01.x, acc.x);
                    acc.y = fmaf(at, f01.y, acc.y);
                    acc.z = fmaf(at, f23.x, acc.z);
                    acc.w = fmaf(at, f23.y, acc.w);
                }
            }
        }
    }

    se += __shfl_xor_sync(FULL, se, 1);
    se += __shfl_xor_sync(FULL, se, 2);
    se += __shfl_xor_sync(FULL, se, 4);
    float i_h = 1.f / fmaxf(se, 1e-20f);

    float4 b = ((const float4*)bias)[lane];
    float4 o;
    o.x = fmaf(acc.x, i_h, b.x); o.x = o.x > 0.f ? o.x : expm1f(o.x);
    o.y = fmaf(acc.y, i_h, b.y); o.y = o.y > 0.f ? o.y : expm1f(o.y);
    o.z = fmaf(acc.z, i_h, b.z); o.z = o.z > 0.f ? o.z : expm1f(o.z);
    o.w = fmaf(acc.w, i_h, b.w); o.w = o.w > 0.f ? o.w : expm1f(o.w);

    if (writeHalf) {
        __half2 h01 = __floats2half2_rn(o.x, o.y);
        __half2 h23 = __floats2half2_rn(o.z, o.w);
        ((uint2*)outH)[(size_t)node * 32 + lane] =
            make_uint2(*(unsigned int*)&h01, *(unsigned int*)&h23);
    } else {
        ((float4*)outF)[(size_t)node * 32 + lane] = o;
    }
}

// ---------------- launcher ----------------
extern "C" void kernel_launch(void* const* d_in, const int* in_sizes, int n_in,
                              void* d_out, int out_size) {
    const float* in_feat = (const float*)d_in[0];
    const float* ew      = (const float*)d_in[1];
    const int*   src     = (const int*)d_in[2];
    const int*   dst     = (const int*)d_in[3];
    const float* W0      = (const float*)d_in[4];
    const float* al0     = (const float*)d_in[5];
    const float* ar0     = (const float*)d_in[6];
    const float* b0      = (const float*)d_in[7];
    const float* W1      = (const float*)d_in[8];
    const float* al1     = (const float*)d_in[9];
    const float* ar1     = (const float*)d_in[10];
    const float* b1      = (const float*)d_in[11];
    float* out = (float*)d_out;

    int N = in_sizes[0] / 128;
    int E = in_sizes[1];

    unsigned int *featH_p, *xH_p, *hH_p;
    float *el_p, *er_p;
    __half* wH_p;
    int* deg_p;
    cudaGetSymbolAddress((void**)&featH_p, g_featH);
    cudaGetSymbolAddress((void**)&xH_p,    g_xH);
    cudaGetSymbolAddress((void**)&hH_p,    g_hH);
    cudaGetSymbolAddress((void**)&el_p,    g_el);
    cudaGetSymbolAddress((void**)&er_p,    g_er);
    cudaGetSymbolAddress((void**)&wH_p,    g_WH);
    cudaGetSymbolAddress((void**)&deg_p,   g_deg);

    // CSR build (graph shared by both layers)
    cudaMemsetAsync(deg_p, 0, (size_t)N * sizeof(int));
    hist_kernel<<<(E + 255) / 256, 256>>>(dst, E);
    scan_kernel<<<1, 1024>>>(N);
    scatter_kernel<<<(E + 255) / 256, 256>>>(src, dst, ew, E);

    // fp16 conversions
    int n32 = N * 32;
    cvt_feat_kernel<<<(n32 + 255) / 256, 256>>>((const float4*)in_feat, (uint2*)xH_p, n32);
    cvt_w_kernel<<<(128 * 128 + 255) / 256, 256>>>(W0, W1);

    int gemm_blocks = (N + 127) / 128;
    int agg_blocks  = (N + 7) / 8;

    // layer 0
    gemm_mma_kernel<<<gemm_blocks, 256>>>(xH_p, wH_p, al0, ar0, featH_p, el_p, er_p, N);
    aggregate_kernel<<<agg_blocks, 256>>>(featH_p, el_p, er_p, b0, (float*)0, hH_p, 1, N);
    // layer 1
    gemm_mma_kernel<<<gemm_blocks, 256>>>(hH_p, wH_p + 128 * 128, al1, ar1, featH_p, el_p, er_p, N);
    aggregate_kernel<<<agg_blocks, 256>>>(featH_p, el_p, er_p, b1, out, (unsigned int*)0, 0, N);
}